// round 1
// baseline (speedup 1.0000x reference)
#include <cuda_runtime.h>

#define N_TOT  262144
#define E_DIM  512
#define H_DIM  256
#define B_BAGS 512

// ---- scratch (no allocations allowed -> __device__ globals) ----
__device__ float g_alpha[N_TOT];
__device__ float g_invden[B_BAGS];
__device__ int   g_start[B_BAGS + 1];

// =====================================================================
// K0: bag start offsets from sorted batch_indices (handles empty bags)
// =====================================================================
__global__ void k_offsets(const int* __restrict__ bi) {
    int n = blockIdx.x * blockDim.x + threadIdx.x;
    if (n >= N_TOT) return;
    int b = bi[n];
    if (n == 0) {
        for (int x = 0; x <= b; ++x) g_start[x] = 0;
    } else {
        int p = bi[n - 1];
        if (p != b) {
            for (int x = p + 1; x <= b; ++x) g_start[x] = n;
        }
    }
    if (n == N_TOT - 1) {
        for (int x = b + 1; x <= B_BAGS; ++x) g_start[x] = N_TOT;
    }
}

// =====================================================================
// K1: fused  alpha[n] = exp( sum_h ww[h]*tanh(dot(X[n],Vw[h]) + Vb[h]) + wb )
// Tiled GEMM: BM=128 rows, BN=128 cols (H in 2 chunks), BK=16.
// Packed f32x2 FFMA2 accumulators (2x fp32 throughput on sm_103a).
// =====================================================================
#define BM 128
#define BN 128
#define BK 16
#define TM 8          // rows per thread
#define NP 4          // column PAIRS per thread (8 cols)

__device__ __forceinline__ float fast_tanh(float x) {
    x = fminf(fmaxf(x, -15.0f), 15.0f);
    float e = __expf(2.0f * x);
    return (e - 1.0f) / (e + 1.0f);
}

__global__ __launch_bounds__(256, 1) void k_scores(
    const float* __restrict__ X, const float* __restrict__ Vw,
    const float* __restrict__ Vb, const float* __restrict__ ww,
    const float* __restrict__ wbp)
{
    __shared__ float Xs[BK][BM + 2];   // pad 2: conflict-free stores, 8B-aligned rows
    __shared__ float Ws[BK][BN + 2];

    const int tid = threadIdx.x;
    const int tx = tid & 15;           // 16 column groups
    const int ty = tid >> 4;           // 16 row groups
    const int row0 = blockIdx.x * BM;

    float part[TM];
#pragma unroll
    for (int i = 0; i < TM; ++i) part[i] = 0.0f;

#pragma unroll
    for (int nh = 0; nh < H_DIM / BN; ++nh) {
        unsigned long long acc2[TM][NP];   // packed f32x2 accumulators
#pragma unroll
        for (int i = 0; i < TM; ++i)
#pragma unroll
            for (int j = 0; j < NP; ++j) acc2[i][j] = 0ull;

        for (int k0 = 0; k0 < E_DIM; k0 += BK) {
            __syncthreads();
            // load X tile: 128 rows x 16 cols (transposed into Xs[k][row])
#pragma unroll
            for (int p = 0; p < 2; ++p) {
                int idx = tid + p * 256;           // 512 float4 slots
                int r = idx >> 2;
                int c = (idx & 3) * 4;
                float4 v = *(const float4*)(X + (size_t)(row0 + r) * E_DIM + k0 + c);
                Xs[c + 0][r] = v.x; Xs[c + 1][r] = v.y;
                Xs[c + 2][r] = v.z; Xs[c + 3][r] = v.w;
            }
            // load Vw tile: rows nh*BN .. +127, cols k0..k0+15
#pragma unroll
            for (int p = 0; p < 2; ++p) {
                int idx = tid + p * 256;
                int r = idx >> 2;
                int c = (idx & 3) * 4;
                float4 v = *(const float4*)(Vw + (size_t)(nh * BN + r) * E_DIM + k0 + c);
                Ws[c + 0][r] = v.x; Ws[c + 1][r] = v.y;
                Ws[c + 2][r] = v.z; Ws[c + 3][r] = v.w;
            }
            __syncthreads();

#pragma unroll
            for (int k = 0; k < BK; ++k) {
                // a: 8 scalar broadcast loads + splat into f32x2
                unsigned long long a2[TM];
#pragma unroll
                for (int i = 0; i < TM; ++i) {
                    float av = Xs[k][ty * TM + i];
                    asm("mov.b64 %0, {%1, %1};" : "=l"(a2[i]) : "r"(__float_as_uint(av)));
                }
                // b: 4 x LDS.64 (column pairs 2*tx + 32*jp)
                unsigned long long b2[NP];
#pragma unroll
                for (int j = 0; j < NP; ++j) {
                    b2[j] = *(const unsigned long long*)(&Ws[k][2 * tx + 32 * j]);
                }
#pragma unroll
                for (int i = 0; i < TM; ++i)
#pragma unroll
                    for (int j = 0; j < NP; ++j)
                        asm("fma.rn.f32x2 %0, %1, %2, %0;"
                            : "+l"(acc2[i][j]) : "l"(a2[i]), "l"(b2[j]));
            }
        }
        // epilogue: tanh + weighted sum over this H chunk
#pragma unroll
        for (int j = 0; j < NP; ++j) {
            int h = nh * BN + 32 * j + 2 * tx;
            float vb0 = __ldg(Vb + h),     vb1 = __ldg(Vb + h + 1);
            float w0  = __ldg(ww + h),     w1  = __ldg(ww + h + 1);
#pragma unroll
            for (int i = 0; i < TM; ++i) {
                unsigned int lo, hi;
                asm("mov.b64 {%0, %1}, %2;" : "=r"(lo), "=r"(hi) : "l"(acc2[i][j]));
                float f0 = __uint_as_float(lo);
                float f1 = __uint_as_float(hi);
                part[i] = fmaf(fast_tanh(f0 + vb0), w0, part[i]);
                part[i] = fmaf(fast_tanh(f1 + vb1), w1, part[i]);
            }
        }
    }

    // deterministic reduction across the 16 tx lanes (each 16-lane half of a warp)
#pragma unroll
    for (int i = 0; i < TM; ++i) {
#pragma unroll
        for (int m = 8; m >= 1; m >>= 1)
            part[i] += __shfl_xor_sync(0xffffffffu, part[i], m);
    }
    if (tx == 0) {
        float wb0 = __ldg(wbp);
#pragma unroll
        for (int i = 0; i < TM; ++i)
            g_alpha[row0 + ty * TM + i] = __expf(part[i] + wb0);
    }
}

// =====================================================================
// K2: per-bag 1/sum(alpha)
// =====================================================================
__global__ __launch_bounds__(256) void k_denom() {
    int b = blockIdx.x;
    int s = g_start[b], e = g_start[b + 1];
    int tid = threadIdx.x;
    float sum = 0.0f;
    for (int n = s + tid; n < e; n += 256) sum += g_alpha[n];
#pragma unroll
    for (int m = 16; m >= 1; m >>= 1) sum += __shfl_xor_sync(0xffffffffu, sum, m);
    __shared__ float ws[8];
    if ((tid & 31) == 0) ws[tid >> 5] = sum;
    __syncthreads();
    if (tid == 0) {
        float t = 0.0f;
#pragma unroll
        for (int w = 0; w < 8; ++w) t += ws[w];
        g_invden[b] = (t > 0.0f) ? (1.0f / t) : 0.0f;
    }
}

// =====================================================================
// K3: per-bag weighted pooling fused with logits + softmax
// 128 threads: each owns 4 consecutive E-columns (float4). Scale by
// inv-denominator once at the end (identical math to per-element division).
// =====================================================================
__global__ __launch_bounds__(128) void k_pool(
    const float* __restrict__ X, const float* __restrict__ dw,
    const float* __restrict__ db, float* __restrict__ out)
{
    int b = blockIdx.x;
    int s = g_start[b], e = g_start[b + 1];
    int tid = threadIdx.x;

    float ax = 0.f, ay = 0.f, az = 0.f, aw = 0.f;
    int n = s;
    for (; n + 4 <= e; n += 4) {
        float w0 = g_alpha[n + 0];
        float w1 = g_alpha[n + 1];
        float w2 = g_alpha[n + 2];
        float w3 = g_alpha[n + 3];
        float4 x0 = *(const float4*)(X + (size_t)(n + 0) * E_DIM + tid * 4);
        float4 x1 = *(const float4*)(X + (size_t)(n + 1) * E_DIM + tid * 4);
        float4 x2 = *(const float4*)(X + (size_t)(n + 2) * E_DIM + tid * 4);
        float4 x3 = *(const float4*)(X + (size_t)(n + 3) * E_DIM + tid * 4);
        ax = fmaf(w0, x0.x, ax); ay = fmaf(w0, x0.y, ay); az = fmaf(w0, x0.z, az); aw = fmaf(w0, x0.w, aw);
        ax = fmaf(w1, x1.x, ax); ay = fmaf(w1, x1.y, ay); az = fmaf(w1, x1.z, az); aw = fmaf(w1, x1.w, aw);
        ax = fmaf(w2, x2.x, ax); ay = fmaf(w2, x2.y, ay); az = fmaf(w2, x2.z, az); aw = fmaf(w2, x2.w, aw);
        ax = fmaf(w3, x3.x, ax); ay = fmaf(w3, x3.y, ay); az = fmaf(w3, x3.z, az); aw = fmaf(w3, x3.w, aw);
    }
    for (; n < e; ++n) {
        float w0 = g_alpha[n];
        float4 x0 = *(const float4*)(X + (size_t)n * E_DIM + tid * 4);
        ax = fmaf(w0, x0.x, ax); ay = fmaf(w0, x0.y, ay); az = fmaf(w0, x0.z, az); aw = fmaf(w0, x0.w, aw);
    }
    float inv = g_invden[b];
    ax *= inv; ay *= inv; az *= inv; aw *= inv;

    float4 d0 = *(const float4*)(dw + tid * 4);
    float4 d1 = *(const float4*)(dw + E_DIM + tid * 4);
    float l0 = ax * d0.x + ay * d0.y + az * d0.z + aw * d0.w;
    float l1 = ax * d1.x + ay * d1.y + az * d1.z + aw * d1.w;

#pragma unroll
    for (int m = 16; m >= 1; m >>= 1) {
        l0 += __shfl_xor_sync(0xffffffffu, l0, m);
        l1 += __shfl_xor_sync(0xffffffffu, l1, m);
    }
    __shared__ float s0[4], s1[4];
    if ((tid & 31) == 0) { s0[tid >> 5] = l0; s1[tid >> 5] = l1; }
    __syncthreads();
    if (tid == 0) {
        float L0 = s0[0] + s0[1] + s0[2] + s0[3] + __ldg(db);
        float L1 = s1[0] + s1[1] + s1[2] + s1[3] + __ldg(db + 1);
        float mx = fmaxf(L0, L1);
        float e0 = __expf(L0 - mx), e1 = __expf(L1 - mx);
        float d = 1.0f / (e0 + e1);
        out[b * 2 + 0] = e0 * d;
        out[b * 2 + 1] = e1 * d;
    }
}

// =====================================================================
extern "C" void kernel_launch(void* const* d_in, const int* in_sizes, int n_in,
                              void* d_out, int out_size) {
    const float* X  = (const float*)d_in[0];   // bag_encoding [N, E]
    const float* Vw = (const float*)d_in[1];   // [H, E]
    const float* Vb = (const float*)d_in[2];   // [H]
    const float* ww = (const float*)d_in[3];   // [1, H]
    const float* wb = (const float*)d_in[4];   // [1]
    const float* dw = (const float*)d_in[5];   // [2, E]
    const float* db = (const float*)d_in[6];   // [2]
    const int*   bi = (const int*)d_in[7];     // batch_indices [N]
    float* out = (float*)d_out;                // [B, 2]

    k_offsets<<<(N_TOT + 255) / 256, 256>>>(bi);
    k_scores<<<N_TOT / BM, 256>>>(X, Vw, Vb, ww, wb);
    k_denom<<<B_BAGS, 256>>>();
    k_pool<<<B_BAGS, 128>>>(X, dw, db, out);
}

// round 3
// speedup vs baseline: 2.1858x; 2.1858x over previous
#include <cuda_runtime.h>
#include <cuda_bf16.h>
#include <cstdint>

#define N_TOT  262144
#define E_DIM  512
#define H_DIM  256
#define B_BAGS 512
#define KC     64

// ---- scratch (__device__ globals; no runtime allocs) ----
__device__ float g_alpha[N_TOT];
__device__ float g_y[N_TOT * 2];
__device__ int   g_start[B_BAGS + 1];
__device__ __align__(16) __nv_bfloat16 g_Bhi[H_DIM * E_DIM];  // pre-swizzled, per-64-col chunk
__device__ __align__(16) __nv_bfloat16 g_Blo[H_DIM * E_DIM];

// =====================================================================
// helpers (plain sm_103-target PTX only: ldmatrix / mma.sync / tanh.approx)
// =====================================================================
__device__ __forceinline__ uint32_t smem_u32(const void* p) {
    uint32_t a;
    asm("{ .reg .u64 t; cvta.to.shared.u64 t, %1; cvt.u32.u64 %0, t; }" : "=r"(a) : "l"(p));
    return a;
}
__device__ __forceinline__ void ldsm4(uint32_t* r, uint32_t a) {
    asm volatile("ldmatrix.sync.aligned.m8n8.x4.shared.b16 {%0,%1,%2,%3}, [%4];"
                 : "=r"(r[0]), "=r"(r[1]), "=r"(r[2]), "=r"(r[3]) : "r"(a));
}
__device__ __forceinline__ void mma_bf16(float* c, const uint32_t* a, const uint32_t* b) {
    asm volatile(
        "mma.sync.aligned.m16n8k16.row.col.f32.bf16.bf16.f32 "
        "{%0,%1,%2,%3},{%4,%5,%6,%7},{%8,%9},{%0,%1,%2,%3};"
        : "+f"(c[0]), "+f"(c[1]), "+f"(c[2]), "+f"(c[3])
        : "r"(a[0]), "r"(a[1]), "r"(a[2]), "r"(a[3]), "r"(b[0]), "r"(b[1]));
}
__device__ __forceinline__ float tanh_fast(float x) {
    float y; asm("tanh.approx.f32 %0, %1;" : "=f"(y) : "f"(x)); return y;
}
__device__ __forceinline__ uint32_t sw128(uint32_t o) { return o ^ ((o >> 3) & 0x70); }

// =====================================================================
// K0: bag start offsets from sorted batch_indices
// =====================================================================
__global__ void k_offsets(const int* __restrict__ bi) {
    int n = blockIdx.x * blockDim.x + threadIdx.x;
    if (n >= N_TOT) return;
    int b = bi[n];
    if (n == 0) {
        for (int x = 0; x <= b; ++x) g_start[x] = 0;
    } else {
        int p = bi[n - 1];
        if (p != b) for (int x = p + 1; x <= b; ++x) g_start[x] = n;
    }
    if (n == N_TOT - 1) for (int x = b + 1; x <= B_BAGS; ++x) g_start[x] = N_TOT;
}

// =====================================================================
// K_split: Vw fp32 -> bf16 hi/lo, pre-swizzled. Chunk c (64 E-cols) is a
// 256-row x 128-byte tile at byte offset c*32768, SW128 within rows.
// =====================================================================
__global__ void k_split(const float* __restrict__ Vw) {
    int idx = blockIdx.x * 256 + threadIdx.x;   // < 131072
    int row = idx >> 9;        // h
    int k   = idx & 511;       // e
    float v = Vw[idx];
    __nv_bfloat16 h = __float2bfloat16(v);
    __nv_bfloat16 l = __float2bfloat16(v - __bfloat162float(h));
    int chunk = k >> 6, col = k & 63;
    uint32_t off = (uint32_t)chunk * 32768u + sw128((uint32_t)(row * 128 + col * 2));
    g_Bhi[off >> 1] = h;
    g_Blo[off >> 1] = l;
}

// =====================================================================
// K1: HMMA bf16x3 fused kernel (mma.sync m16n8k16, register accum).
//  CTA tile: 128 rows x 256 H, K=512 in 8 chunks of 64, double-buffered.
//  Warp grid 2x4 -> warp tile 64x64. 3 split MMAs: hi*hi + lo*hi + hi*lo.
//  Fused: y[n,c]=dot(x_n,dw_c) during A load; epilogue tanh/ww/exp.
// =====================================================================
#define BUF_STRIDE 98304
#define OFF_AH 0
#define OFF_AL 16384
#define OFF_BH 32768
#define OFF_BL 65536
#define OFF_WW 196608
#define OFF_VB 197632
#define OFF_DW 198656
#define OFF_RED 202752
#define SMEM_TOTAL 204800

__global__ __launch_bounds__(256, 1) void k_scores_mma(
    const float* __restrict__ X, const float* __restrict__ ww,
    const float* __restrict__ Vb, const float* __restrict__ wbp,
    const float* __restrict__ dw)
{
    extern __shared__ char smem[];
    const uint32_t sb = smem_u32(smem);
    const int tid = threadIdx.x, wid = tid >> 5, l = tid & 31;
    const int wm = wid & 1, wn = wid >> 1;

    float* wwS = (float*)(smem + OFF_WW);
    float* VbS = (float*)(smem + OFF_VB);
    float* dwS = (float*)(smem + OFF_DW);
    wwS[tid] = __ldg(ww + tid);
    VbS[tid] = __ldg(Vb + tid);
#pragma unroll
    for (int i = 0; i < 4; ++i) dwS[tid + i * 256] = __ldg(dw + tid + i * 256);
    __syncthreads();

    const int row0 = blockIdx.x * 128;
    const int lrow = tid >> 1, half = tid & 1;
    const float* xrow = X + (size_t)(row0 + lrow) * E_DIM + half * 32;

    float C[4][8][4];
#pragma unroll
    for (int a = 0; a < 4; ++a)
#pragma unroll
        for (int b = 0; b < 8; ++b)
#pragma unroll
            for (int k = 0; k < 4; ++k) C[a][b][k] = 0.f;
    float y0 = 0.f, y1 = 0.f;

    // ldmatrix per-thread address components (bytes)
    const uint32_t rbA = (uint32_t)((wm * 64 + (l & 15)) * 128);
    const uint32_t ksA = (l & 16) ? 16u : 0u;
    const uint32_t rbB = (uint32_t)((wn * 64 + ((l >> 4) << 3) + (l & 7)) * 128);
    const uint32_t ksB = (l & 8) ? 16u : 0u;

    // ---- chunk loader: A fp32->bf16 hi/lo + fused dw dots; B straight copy ----
    auto load_chunk = [&](int c, int buf) {
        char* aHp = smem + buf * BUF_STRIDE + OFF_AH;
        char* aLp = smem + buf * BUF_STRIDE + OFF_AL;
        const float* xp = xrow + c * 64;
#pragma unroll
        for (int j = 0; j < 8; ++j) {
            const int colk = half * 32 + j * 4;
            const int colg = c * 64 + colk;
            float4 v  = *(const float4*)(xp + j * 4);
            float4 d0 = *(const float4*)(dwS + colg);
            float4 d1 = *(const float4*)(dwS + 512 + colg);
            y0 += v.x * d0.x + v.y * d0.y + v.z * d0.z + v.w * d0.w;
            y1 += v.x * d1.x + v.y * d1.y + v.z * d1.z + v.w * d1.w;
            __nv_bfloat16 hx = __float2bfloat16(v.x), hy = __float2bfloat16(v.y);
            __nv_bfloat16 hz = __float2bfloat16(v.z), hw = __float2bfloat16(v.w);
            __nv_bfloat16 lx = __float2bfloat16(v.x - __bfloat162float(hx));
            __nv_bfloat16 ly = __float2bfloat16(v.y - __bfloat162float(hy));
            __nv_bfloat16 lz = __float2bfloat16(v.z - __bfloat162float(hz));
            __nv_bfloat16 lw = __float2bfloat16(v.w - __bfloat162float(hw));
            uint2 hv, lv;
            hv.x = ((uint32_t)__bfloat16_as_ushort(hy) << 16) | __bfloat16_as_ushort(hx);
            hv.y = ((uint32_t)__bfloat16_as_ushort(hw) << 16) | __bfloat16_as_ushort(hz);
            lv.x = ((uint32_t)__bfloat16_as_ushort(ly) << 16) | __bfloat16_as_ushort(lx);
            lv.y = ((uint32_t)__bfloat16_as_ushort(lw) << 16) | __bfloat16_as_ushort(lz);
            uint32_t off = sw128((uint32_t)(lrow * 128 + colk * 2));
            *(uint2*)(aHp + off) = hv;
            *(uint2*)(aLp + off) = lv;
        }
        uint4* bh = (uint4*)(smem + buf * BUF_STRIDE + OFF_BH);
        uint4* bl = (uint4*)(smem + buf * BUF_STRIDE + OFF_BL);
        const uint4* gh = ((const uint4*)g_Bhi) + c * 2048;
        const uint4* gl = ((const uint4*)g_Blo) + c * 2048;
#pragma unroll
        for (int i = 0; i < 8; ++i) {
            bh[tid + i * 256] = gh[tid + i * 256];
            bl[tid + i * 256] = gl[tid + i * 256];
        }
    };

    load_chunk(0, 0);
    __syncthreads();

    for (int c = 0; c < 8; ++c) {
        const int buf = c & 1;
        if (c < 7) load_chunk(c + 1, buf ^ 1);

        const uint32_t aH = sb + buf * BUF_STRIDE + OFF_AH;
        const uint32_t aL = sb + buf * BUF_STRIDE + OFF_AL;
        const uint32_t bH = sb + buf * BUF_STRIDE + OFF_BH;
        const uint32_t bL = sb + buf * BUF_STRIDE + OFF_BL;
#pragma unroll
        for (int ks = 0; ks < 4; ++ks) {
            uint32_t Ah[4][4], Al[4][4], Bf[4][4];
            // 16-row frag steps don't touch swizzle bits [9:7] -> hoist sw128
            const uint32_t swA = sw128(rbA + ks * 32 + ksA);
            const uint32_t swB = sw128(rbB + ks * 32 + ksB);
#pragma unroll
            for (int mf = 0; mf < 4; ++mf) {
                ldsm4(Ah[mf], aH + swA + mf * 2048);
                ldsm4(Al[mf], aL + swA + mf * 2048);
            }
#pragma unroll
            for (int g = 0; g < 4; ++g) ldsm4(Bf[g], bH + swB + g * 2048);
#pragma unroll
            for (int mf = 0; mf < 4; ++mf)
#pragma unroll
                for (int g = 0; g < 4; ++g) {
                    mma_bf16(C[mf][2 * g],     Ah[mf], Bf[g]);
                    mma_bf16(C[mf][2 * g + 1], Ah[mf], Bf[g] + 2);
                    mma_bf16(C[mf][2 * g],     Al[mf], Bf[g]);
                    mma_bf16(C[mf][2 * g + 1], Al[mf], Bf[g] + 2);
                }
#pragma unroll
            for (int g = 0; g < 4; ++g) ldsm4(Bf[g], bL + swB + g * 2048);
#pragma unroll
            for (int mf = 0; mf < 4; ++mf)
#pragma unroll
                for (int g = 0; g < 4; ++g) {
                    mma_bf16(C[mf][2 * g],     Ah[mf], Bf[g]);
                    mma_bf16(C[mf][2 * g + 1], Ah[mf], Bf[g] + 2);
                }
        }
        __syncthreads();
    }

    // ---- y writeback (pair reduce across the 2 threads of each row) ----
    float o0 = y0 + __shfl_xor_sync(0xffffffffu, y0, 1);
    float o1 = y1 + __shfl_xor_sync(0xffffffffu, y1, 1);
    if (half == 0) {
        *(float2*)(g_y + (size_t)(row0 + lrow) * 2) = make_float2(o0, o1);
    }

    // ---- epilogue: tanh + ww-weighted col sum, cross-warp reduce, exp ----
    float* red = (float*)(smem + OFF_RED);
#pragma unroll
    for (int mf = 0; mf < 4; ++mf) {
        float p0 = 0.f, p1 = 0.f;
#pragma unroll
        for (int nf = 0; nf < 8; ++nf) {
            int h = wn * 64 + nf * 8 + (l & 3) * 2;
            float vb0 = VbS[h], vb1 = VbS[h + 1];
            float w0 = wwS[h],  w1 = wwS[h + 1];
            p0 = fmaf(w0, tanh_fast(C[mf][nf][0] + vb0), p0);
            p0 = fmaf(w1, tanh_fast(C[mf][nf][1] + vb1), p0);
            p1 = fmaf(w0, tanh_fast(C[mf][nf][2] + vb0), p1);
            p1 = fmaf(w1, tanh_fast(C[mf][nf][3] + vb1), p1);
        }
        p0 += __shfl_xor_sync(0xffffffffu, p0, 1);
        p0 += __shfl_xor_sync(0xffffffffu, p0, 2);
        p1 += __shfl_xor_sync(0xffffffffu, p1, 1);
        p1 += __shfl_xor_sync(0xffffffffu, p1, 2);
        if ((l & 3) == 0) {
            int r = wm * 64 + mf * 16 + (l >> 2);
            red[r * 4 + wn] = p0;
            red[(r + 8) * 4 + wn] = p1;
        }
    }
    __syncthreads();
    if (tid < 128) {
        float s = red[tid * 4] + red[tid * 4 + 1] + red[tid * 4 + 2] + red[tid * 4 + 3];
        g_alpha[row0 + tid] = __expf(s + __ldg(wbp));
    }
}

// =====================================================================
// K_final: per-bag segment sums of (alpha, alpha*y) -> logits -> softmax
// =====================================================================
__global__ __launch_bounds__(256) void k_final(const float* __restrict__ dbp,
                                               float* __restrict__ out) {
    int b = blockIdx.x, tid = threadIdx.x;
    int s = g_start[b], e = g_start[b + 1];
    float den = 0.f, L0 = 0.f, L1 = 0.f;
    for (int n = s + tid; n < e; n += 256) {
        float a = g_alpha[n];
        float2 y = *(const float2*)(g_y + (size_t)n * 2);
        den += a; L0 += a * y.x; L1 += a * y.y;
    }
#pragma unroll
    for (int m = 16; m >= 1; m >>= 1) {
        den += __shfl_xor_sync(0xffffffffu, den, m);
        L0  += __shfl_xor_sync(0xffffffffu, L0, m);
        L1  += __shfl_xor_sync(0xffffffffu, L1, m);
    }
    __shared__ float sd[8], s0[8], s1[8];
    if ((tid & 31) == 0) { sd[tid >> 5] = den; s0[tid >> 5] = L0; s1[tid >> 5] = L1; }
    __syncthreads();
    if (tid == 0) {
        float D = 0.f, A = 0.f, B = 0.f;
#pragma unroll
        for (int w = 0; w < 8; ++w) { D += sd[w]; A += s0[w]; B += s1[w]; }
        float inv = (D > 0.f) ? (1.f / D) : 0.f;
        float LA = A * inv + __ldg(dbp);
        float LB = B * inv + __ldg(dbp + 1);
        float mx = fmaxf(LA, LB);
        float e0 = __expf(LA - mx), e1 = __expf(LB - mx);
        float dn = 1.f / (e0 + e1);
        out[b * 2 + 0] = e0 * dn;
        out[b * 2 + 1] = e1 * dn;
    }
}

// =====================================================================
extern "C" void kernel_launch(void* const* d_in, const int* in_sizes, int n_in,
                              void* d_out, int out_size) {
    const float* X  = (const float*)d_in[0];   // [N, E]
    const float* Vw = (const float*)d_in[1];   // [H, E]
    const float* Vb = (const float*)d_in[2];   // [H]
    const float* ww = (const float*)d_in[3];   // [1, H]
    const float* wb = (const float*)d_in[4];   // [1]
    const float* dw = (const float*)d_in[5];   // [2, E]
    const float* db = (const float*)d_in[6];   // [2]
    const int*   bi = (const int*)d_in[7];     // [N]
    float* out = (float*)d_out;                // [B, 2]

    cudaFuncSetAttribute(k_scores_mma, cudaFuncAttributeMaxDynamicSharedMemorySize, SMEM_TOTAL);

    k_offsets<<<(N_TOT + 255) / 256, 256>>>(bi);
    k_split<<<(H_DIM * E_DIM) / 256, 256>>>(Vw);
    k_scores_mma<<<N_TOT / 128, 256, SMEM_TOTAL>>>(X, ww, Vb, wb, dw);
    k_final<<<B_BAGS, 256>>>(db, out);
}